// round 4
// baseline (speedup 1.0000x reference)
#include <cuda_runtime.h>
#include <math_constants.h>
#include <cstdint>

#define NROWS 8192
#define NSPLIT 2
#define TILES 32                  // 128-wide col tiles per split
#define MARGIN_F 0.3f
#define LS 254.0f                 // residual scale
#define INV_LS (1.0f / 254.0f)

#define ROWB 144                  // padded row stride (128 s8 used) -> conflict-free ldsm
#define CH (128 * ROWB)           // 18432 B per 128x128 s8 chunk
#define BLK (2 * CH)              // [H|L] chunks per 128-row block = 36864 B

// smem map
#define SM_PART 0                           // 4*128 floats = 2048
#define SM_SQ2S 2048                        // 4096 floats = 16384
#define SM_INVB (SM_SQ2S + 16384)           // 4096 floats = 16384
#define SM_A    (SM_INVB + 16384)           // 36864
#define SM_B    (SM_A + BLK)                // 2 * 36864
#define SMEM_TOTAL (SM_B + 2 * BLK)         // 145408

__device__ __align__(16) unsigned char g_A[64 * BLK];   // 2.36 MB
__device__ __align__(16) unsigned char g_B[64 * BLK];
__device__ float g_sq1[NROWS];
__device__ float g_sq2[NROWS];
__device__ float g_invA[NROWS];
__device__ float g_invB[NROWS];
__device__ float g_posv[NROWS];
__device__ float g_rowmin[NSPLIT][NROWS];

__device__ __forceinline__ uint32_t smem_u32(const void* p) {
    uint32_t a;
    asm("{ .reg .u64 t; cvta.to.shared.u64 t, %1; cvt.u32.u64 %0, t; }" : "=r"(a) : "l"(p));
    return a;
}
__device__ __forceinline__ void cpasync16(uint32_t dst, const void* src) {
    asm volatile("cp.async.cg.shared.global [%0], [%1], 16;" :: "r"(dst), "l"(src));
}
#define CP_COMMIT() asm volatile("cp.async.commit_group;" ::: "memory")
#define CP_WAIT0()  asm volatile("cp.async.wait_group 0;"  ::: "memory")

__device__ __forceinline__ void ldsm_x4(uint32_t addr, uint32_t& r0, uint32_t& r1,
                                        uint32_t& r2, uint32_t& r3) {
    asm volatile("ldmatrix.sync.aligned.m8n8.x4.shared.b16 {%0,%1,%2,%3}, [%4];"
                 : "=r"(r0), "=r"(r1), "=r"(r2), "=r"(r3) : "r"(addr));
}
// s8 m16n8k32, s32 accumulate (C = D)
__device__ __forceinline__ void imma(int* c, uint32_t a0, uint32_t a1, uint32_t a2,
                                     uint32_t a3, uint32_t b0, uint32_t b1) {
    asm volatile("mma.sync.aligned.m16n8k32.row.col.s32.s8.s8.s32 "
                 "{%0,%1,%2,%3}, {%4,%5,%6,%7}, {%8,%9}, {%0,%1,%2,%3};"
                 : "+r"(c[0]), "+r"(c[1]), "+r"(c[2]), "+r"(c[3])
                 : "r"(a0), "r"(a1), "r"(a2), "r"(a3), "r"(b0), "r"(b1));
}
// s8 m16n8k32, C = 0 (fresh write, avoids acc reset MOVs)
__device__ __forceinline__ void imma_z(int* c, uint32_t a0, uint32_t a1, uint32_t a2,
                                       uint32_t a3, uint32_t b0, uint32_t b1) {
    asm volatile("mma.sync.aligned.m16n8k32.row.col.s32.s8.s8.s32 "
                 "{%0,%1,%2,%3}, {%4,%5,%6,%7}, {%8,%9}, {%10,%10,%10,%10};"
                 : "=r"(c[0]), "=r"(c[1]), "=r"(c[2]), "=r"(c[3])
                 : "r"(a0), "r"(a1), "r"(a2), "r"(a3), "r"(b0), "r"(b1), "r"(0));
}

// ---------------------------------------------------------------------------
// Prep: one warp per row. Row absmax -> scale; h/l s8 split; sq norms; inv scales.
// Layout: [rowblock 0..63][chunk H|L][row 0..127][144 B (128 used)]
// ---------------------------------------------------------------------------
__global__ void prep_kernel(const float* __restrict__ z1, const float* __restrict__ z2) {
    const int gw = (blockIdx.x * blockDim.x + threadIdx.x) >> 5;
    const int l  = threadIdx.x & 31;
    if (gw >= NROWS) return;
    const int rb = gw >> 7, r = gw & 127;
    const size_t base = (size_t)rb * BLK + (size_t)r * ROWB + (size_t)l * 4;

    #pragma unroll
    for (int which = 0; which < 2; which++) {
        const float* z = which ? z2 : z1;
        float4 v = reinterpret_cast<const float4*>(z + (size_t)gw * 128)[l];
        float x[4] = {v.x, v.y, v.z, v.w};
        float sq = x[0]*x[0] + x[1]*x[1] + x[2]*x[2] + x[3]*x[3];
        float am = fmaxf(fmaxf(fabsf(x[0]), fabsf(x[1])), fmaxf(fabsf(x[2]), fabsf(x[3])));
        #pragma unroll
        for (int o = 16; o; o >>= 1) {
            sq += __shfl_xor_sync(0xffffffffu, sq, o);
            am = fmaxf(am, __shfl_xor_sync(0xffffffffu, am, o));
        }
        am = fmaxf(am, 1e-20f);
        const float s = 127.0f / am;
        uint32_t hq = 0, lq = 0;
        #pragma unroll
        for (int t = 0; t < 4; t++) {
            float xs = x[t] * s;
            float hf = rintf(xs);
            float lf = rintf((xs - hf) * LS);
            hq |= ((uint32_t)(uint8_t)(int8_t)(int)hf) << (8 * t);
            lq |= ((uint32_t)(uint8_t)(int8_t)(int)lf) << (8 * t);
        }
        unsigned char* G = which ? g_B : g_A;
        *(uint32_t*)(G + base + 0 * CH) = hq;   // H chunk
        *(uint32_t*)(G + base + 1 * CH) = lq;   // L chunk
        if (l == 0) {
            if (which) { g_sq2[gw] = sq; g_invB[gw] = am * (1.0f / 127.0f); }
            else       { g_sq1[gw] = sq; g_invA[gw] = am * (1.0f / 127.0f); }
        }
    }
}

// ---------------------------------------------------------------------------
// Main: 128 CTAs (64 row-blocks x 2 col-splits), 8 warps, warp tile 64x32.
// Dual s32 chains: acc1 = H.H (4 k32 steps), acc2 = L.H + H.L (8 steps).
// Fused dequant + row-min + diag epilogue, all register-resident.
// ---------------------------------------------------------------------------
__global__ __launch_bounds__(256, 1) void tl_gemm_kernel() {
    extern __shared__ char smem[];
    float* partmin = (float*)(smem + SM_PART);
    const float* sq2s = (const float*)(smem + SM_SQ2S);
    const float* invBs = (const float*)(smem + SM_INVB);
    const uint32_t smA = smem_u32(smem) + SM_A;
    const uint32_t smB = smem_u32(smem) + SM_B;

    const int tid = threadIdx.x;
    const int l = tid & 31, wid = tid >> 5;
    const int wr = wid & 1, wc = wid >> 1;       // 2 row halves x 4 col groups
    const int rowBase = blockIdx.x * 128;
    const int sp = blockIdx.y;

    // prologue: A block + sq2/invB split arrays + B tile 0, one commit group
    {
        const unsigned char* Ag = g_A + (size_t)blockIdx.x * BLK;
        #pragma unroll
        for (int e = 0; e < 9; e++) {
            int idx = e * 256 + tid;                       // 2304 x 16B
            cpasync16(smA + idx * 16, Ag + (size_t)idx * 16);
        }
        const float* q2 = g_sq2 + sp * (TILES * 128);
        const float* ib = g_invB + sp * (TILES * 128);
        #pragma unroll
        for (int e = 0; e < 4; e++) {
            int idx = e * 256 + tid;                       // 1024 x 16B each
            cpasync16(smem_u32(smem) + SM_SQ2S + idx * 16, q2 + idx * 4);
            cpasync16(smem_u32(smem) + SM_INVB + idx * 16, ib + idx * 4);
        }
        const unsigned char* Bg = g_B + (size_t)(sp * TILES) * BLK;
        #pragma unroll
        for (int e = 0; e < 9; e++) {
            int idx = e * 256 + tid;
            cpasync16(smB + idx * 16, Bg + (size_t)idx * 16);
        }
        CP_COMMIT();
    }

    // per-thread row scales (8 rows this thread accumulates)
    const int mL = rowBase + wr * 64 + (l >> 2);
    float iaL[4], iaH[4];
    #pragma unroll
    for (int i = 0; i < 4; i++) {
        iaL[i] = g_invA[mL + i * 16];
        iaH[i] = g_invA[mL + i * 16 + 8];
    }

    float rminL[4], rminH[4];
    #pragma unroll
    for (int i = 0; i < 4; i++) { rminL[i] = CUDART_INF_F; rminH[i] = CUDART_INF_F; }

    const uint32_t aOff = (uint32_t)((wr * 64 + (l & 15)) * ROWB + (l >> 4) * 16);
    const uint32_t bOff = (uint32_t)((wc * 32 + (l & 15)) * ROWB + (l >> 4) * 16);

    int acc1[4][4][4], acc2[4][4][4];

    for (int jt = 0; jt < TILES; jt++) {
        CP_WAIT0();
        __syncthreads();

        if (jt + 1 < TILES) {   // prefetch next 36KB tile
            const unsigned char* Bg = g_B + (size_t)(sp * TILES + jt + 1) * BLK;
            const uint32_t dst = smB + (uint32_t)(((jt + 1) & 1) ? BLK : 0);
            #pragma unroll
            for (int e = 0; e < 9; e++) {
                int idx = e * 256 + tid;
                cpasync16(dst + idx * 16, Bg + (size_t)idx * 16);
            }
            CP_COMMIT();
        }

        const uint32_t aH = smA + aOff, aL = aH + CH;
        const uint32_t bT = smB + (uint32_t)((jt & 1) ? BLK : 0);
        const uint32_t bH = bT + bOff, bL = bH + CH;

        // ---- chain 1: H.H -> acc1 (4 k32 steps)
        #pragma unroll
        for (int ks = 0; ks < 4; ks++) {
            uint32_t b[8];
            ldsm_x4(bH + ks * 32, b[0], b[1], b[2], b[3]);
            ldsm_x4(bH + 16 * ROWB + ks * 32, b[4], b[5], b[6], b[7]);
            #pragma unroll
            for (int i = 0; i < 4; i++) {
                uint32_t a0, a1, a2, a3;
                ldsm_x4(aH + i * 16 * ROWB + ks * 32, a0, a1, a2, a3);
                if (ks == 0) {
                    imma_z(acc1[i][0], a0, a1, a2, a3, b[0], b[2]);
                    imma_z(acc1[i][1], a0, a1, a2, a3, b[1], b[3]);
                    imma_z(acc1[i][2], a0, a1, a2, a3, b[4], b[6]);
                    imma_z(acc1[i][3], a0, a1, a2, a3, b[5], b[7]);
                } else {
                    imma(acc1[i][0], a0, a1, a2, a3, b[0], b[2]);
                    imma(acc1[i][1], a0, a1, a2, a3, b[1], b[3]);
                    imma(acc1[i][2], a0, a1, a2, a3, b[4], b[6]);
                    imma(acc1[i][3], a0, a1, a2, a3, b[5], b[7]);
                }
            }
        }
        // ---- chain 2a: L.H -> acc2 (4 steps, first zeroes)
        #pragma unroll
        for (int ks = 0; ks < 4; ks++) {
            uint32_t b[8];
            ldsm_x4(bH + ks * 32, b[0], b[1], b[2], b[3]);
            ldsm_x4(bH + 16 * ROWB + ks * 32, b[4], b[5], b[6], b[7]);
            #pragma unroll
            for (int i = 0; i < 4; i++) {
                uint32_t a0, a1, a2, a3;
                ldsm_x4(aL + i * 16 * ROWB + ks * 32, a0, a1, a2, a3);
                if (ks == 0) {
                    imma_z(acc2[i][0], a0, a1, a2, a3, b[0], b[2]);
                    imma_z(acc2[i][1], a0, a1, a2, a3, b[1], b[3]);
                    imma_z(acc2[i][2], a0, a1, a2, a3, b[4], b[6]);
                    imma_z(acc2[i][3], a0, a1, a2, a3, b[5], b[7]);
                } else {
                    imma(acc2[i][0], a0, a1, a2, a3, b[0], b[2]);
                    imma(acc2[i][1], a0, a1, a2, a3, b[1], b[3]);
                    imma(acc2[i][2], a0, a1, a2, a3, b[4], b[6]);
                    imma(acc2[i][3], a0, a1, a2, a3, b[5], b[7]);
                }
            }
        }
        // ---- chain 2b: H.L -> acc2 (4 steps, accumulate)
        #pragma unroll
        for (int ks = 0; ks < 4; ks++) {
            uint32_t b[8];
            ldsm_x4(bL + ks * 32, b[0], b[1], b[2], b[3]);
            ldsm_x4(bL + 16 * ROWB + ks * 32, b[4], b[5], b[6], b[7]);
            #pragma unroll
            for (int i = 0; i < 4; i++) {
                uint32_t a0, a1, a2, a3;
                ldsm_x4(aH + i * 16 * ROWB + ks * 32, a0, a1, a2, a3);
                imma(acc2[i][0], a0, a1, a2, a3, b[0], b[2]);
                imma(acc2[i][1], a0, a1, a2, a3, b[1], b[3]);
                imma(acc2[i][2], a0, a1, a2, a3, b[4], b[6]);
                imma(acc2[i][3], a0, a1, a2, a3, b[5], b[7]);
            }
        }

        // ---- epilogue: dequant, diag capture, running min
        {
            const int colT = (sp * TILES + jt) * 128;
            const int nb = wc * 32 + 2 * (l & 3);       // local col in tile
            const bool diagT = (colT == rowBase);
            #pragma unroll
            for (int j = 0; j < 4; j++) {
                const int nl = nb + j * 8;
                const int n0 = colT + nl;
                const float2 q2 = *(const float2*)(sq2s + jt * 128 + nl);
                const float2 ib = *(const float2*)(invBs + jt * 128 + nl);
                #pragma unroll
                for (int i = 0; i < 4; i++) {
                    const float f0 = (float)acc1[i][j][0] + (float)acc2[i][j][0] * INV_LS;
                    const float f1 = (float)acc1[i][j][1] + (float)acc2[i][j][1] * INV_LS;
                    const float f2 = (float)acc1[i][j][2] + (float)acc2[i][j][2] * INV_LS;
                    const float f3 = (float)acc1[i][j][3] + (float)acc2[i][j][3] * INV_LS;
                    float v0 = q2.x - 2.f * iaL[i] * ib.x * f0;
                    float v1 = q2.y - 2.f * iaL[i] * ib.y * f1;
                    float v2 = q2.x - 2.f * iaH[i] * ib.x * f2;
                    float v3 = q2.y - 2.f * iaH[i] * ib.y * f3;
                    if (diagT) {
                        const int m0 = mL + i * 16, m1 = m0 + 8;
                        if (n0 == m0)     { g_posv[m0] = v0; v0 = CUDART_INF_F; }
                        if (n0 + 1 == m0) { g_posv[m0] = v1; v1 = CUDART_INF_F; }
                        if (n0 == m1)     { g_posv[m1] = v2; v2 = CUDART_INF_F; }
                        if (n0 + 1 == m1) { g_posv[m1] = v3; v3 = CUDART_INF_F; }
                    }
                    rminL[i] = fminf(rminL[i], fminf(v0, v1));
                    rminH[i] = fminf(rminH[i], fminf(v2, v3));
                }
            }
        }
    }

    // cross-lane then cross-warp-column min reduction
    #pragma unroll
    for (int i = 0; i < 4; i++) {
        float vL = rminL[i], vH = rminH[i];
        vL = fminf(vL, __shfl_xor_sync(0xffffffffu, vL, 1));
        vL = fminf(vL, __shfl_xor_sync(0xffffffffu, vL, 2));
        vH = fminf(vH, __shfl_xor_sync(0xffffffffu, vH, 1));
        vH = fminf(vH, __shfl_xor_sync(0xffffffffu, vH, 2));
        if ((l & 3) == 0) {
            const int r = wr * 64 + i * 16 + (l >> 2);
            partmin[wc * 128 + r]     = vL;
            partmin[wc * 128 + r + 8] = vH;
        }
    }
    __syncthreads();
    if (tid < 128) {
        float m = fminf(fminf(partmin[tid], partmin[128 + tid]),
                        fminf(partmin[256 + tid], partmin[384 + tid]));
        g_rowmin[sp][rowBase + tid] = m;
    }
}

// ---------------------------------------------------------------------------
__global__ void finalize_kernel(float* __restrict__ out) {
    __shared__ float red[256];
    const int tid = threadIdx.x;
    float s = 0.f;
    for (int i = tid; i < NROWS; i += 256) {
        float m = fminf(g_rowmin[0][i], g_rowmin[1][i]);
        const float sq1 = g_sq1[i];
        const float l = sqrtf(fmaxf(sq1 + g_posv[i], 0.f))
                      - sqrtf(fmaxf(sq1 + m, 0.f)) + MARGIN_F;
        s += fmaxf(l, 0.f);
    }
    red[tid] = s;
    __syncthreads();
    #pragma unroll
    for (int o = 128; o; o >>= 1) {
        if (tid < o) red[tid] += red[tid + o];
        __syncthreads();
    }
    if (tid == 0) out[0] = red[0] / (float)NROWS;
}

// ---------------------------------------------------------------------------
extern "C" void kernel_launch(void* const* d_in, const int* in_sizes, int n_in,
                              void* d_out, int out_size) {
    const float* z1 = (const float*)d_in[0];
    const float* z2 = (const float*)d_in[1];
    float* out = (float*)d_out;

    cudaFuncSetAttribute(tl_gemm_kernel,
                         cudaFuncAttributeMaxDynamicSharedMemorySize, SMEM_TOTAL);

    prep_kernel<<<NROWS / 8, 256>>>(z1, z2);
    tl_gemm_kernel<<<dim3(64, NSPLIT), 256, SMEM_TOTAL>>>();
    finalize_kernel<<<1, 256>>>(out);
}

// round 5
// speedup vs baseline: 3.4191x; 3.4191x over previous
#include <cuda_runtime.h>
#include <cuda_fp16.h>
#include <math_constants.h>
#include <cstdint>

#define NROWS 8192
#define NSPLIT 2
#define TILES 32                  // 128-wide col tiles per split
#define MARGIN_F 0.3f

#define ROWB 272                  // padded row stride bytes (256 used) -> conflict-free ldsm
#define CH (128 * ROWB)           // 34816 B per 128x128 fp16 chunk
#define ABLK (2 * CH)             // A: [hi|lo] chunks per 128-row block
#define BBLK CH                   // B: hi chunk only

// smem map
#define SM_PART 0                           // 4*128 floats = 2048
#define SM_SQ2S 2048                        // 4096 floats = 16384
#define SM_A    (SM_SQ2S + 16384)           // 69632 (resident, hi+lo)
#define SM_B    (SM_A + ABLK)               // 2 x 34816 (double buffer)
#define SMEM_TOTAL (SM_B + 2 * CH)          // 157696

typedef unsigned long long u64;

__device__ __align__(16) unsigned char g_A[64 * ABLK];   // 4.25 MB
__device__ __align__(16) unsigned char g_B[64 * BBLK];   // 2.1 MB
__device__ float g_sq1[NROWS];
__device__ float g_sq2[NROWS];
__device__ float g_posv[NROWS];
__device__ float g_rowmin[NSPLIT][NROWS];

__device__ __forceinline__ uint32_t smem_u32(const void* p) {
    uint32_t a;
    asm("{ .reg .u64 t; cvta.to.shared.u64 t, %1; cvt.u32.u64 %0, t; }" : "=r"(a) : "l"(p));
    return a;
}
__device__ __forceinline__ void cpasync16(uint32_t dst, const void* src) {
    asm volatile("cp.async.cg.shared.global [%0], [%1], 16;" :: "r"(dst), "l"(src));
}
#define CP_COMMIT() asm volatile("cp.async.commit_group;" ::: "memory")
#define CP_WAIT0()  asm volatile("cp.async.wait_group 0;"  ::: "memory")

__device__ __forceinline__ void ldsm_x4(uint32_t addr, uint32_t& r0, uint32_t& r1,
                                        uint32_t& r2, uint32_t& r3) {
    asm volatile("ldmatrix.sync.aligned.m8n8.x4.shared.b16 {%0,%1,%2,%3}, [%4];"
                 : "=r"(r0), "=r"(r1), "=r"(r2), "=r"(r3) : "r"(addr));
}
__device__ __forceinline__ void hmma(float* c, uint32_t a0, uint32_t a1, uint32_t a2,
                                     uint32_t a3, uint32_t b0, uint32_t b1) {
    asm volatile("mma.sync.aligned.m16n8k16.row.col.f32.f16.f16.f32 "
                 "{%0,%1,%2,%3}, {%4,%5,%6,%7}, {%8,%9}, {%0,%1,%2,%3};"
                 : "+f"(c[0]), "+f"(c[1]), "+f"(c[2]), "+f"(c[3])
                 : "r"(a0), "r"(a1), "r"(a2), "r"(a3), "r"(b0), "r"(b1));
}
__device__ __forceinline__ void hmma_z(float* c, uint32_t a0, uint32_t a1, uint32_t a2,
                                       uint32_t a3, uint32_t b0, uint32_t b1) {
    asm volatile("mma.sync.aligned.m16n8k16.row.col.f32.f16.f16.f32 "
                 "{%0,%1,%2,%3}, {%4,%5,%6,%7}, {%8,%9}, {%10,%10,%10,%10};"
                 : "=f"(c[0]), "=f"(c[1]), "=f"(c[2]), "=f"(c[3])
                 : "r"(a0), "r"(a1), "r"(a2), "r"(a3), "r"(b0), "r"(b1), "f"(0.f));
}

// ---------------------------------------------------------------------------
// Prep: one warp per row. sq norms + fp16 hi/lo split.
// A layout: [rowblock][hi|lo chunk][row][272 B]; B: [rowblock][hi][row][272 B].
// ---------------------------------------------------------------------------
__global__ void prep_kernel(const float* __restrict__ z1, const float* __restrict__ z2) {
    const int gw = (blockIdx.x * blockDim.x + threadIdx.x) >> 5;
    const int l  = threadIdx.x & 31;
    if (gw >= NROWS) return;
    const int rb = gw >> 7, r = gw & 127;
    const size_t rowoff = (size_t)r * ROWB + (size_t)l * 8;

    {   // z1 -> A (hi + lo)
        float4 v = reinterpret_cast<const float4*>(z1 + (size_t)gw * 128)[l];
        float x[4] = {v.x, v.y, v.z, v.w};
        float sq = x[0]*x[0] + x[1]*x[1] + x[2]*x[2] + x[3]*x[3];
        #pragma unroll
        for (int o = 16; o; o >>= 1) sq += __shfl_xor_sync(0xffffffffu, sq, o);
        if (l == 0) g_sq1[gw] = sq;
        u64 hq = 0, lq = 0;
        #pragma unroll
        for (int t = 0; t < 4; t++) {
            __half h  = __float2half_rn(x[t]);
            __half lo = __float2half_rn(x[t] - __half2float(h));
            hq |= (u64)__half_as_ushort(h)  << (16 * t);
            lq |= (u64)__half_as_ushort(lo) << (16 * t);
        }
        unsigned char* base = g_A + (size_t)rb * ABLK + rowoff;
        *(u64*)(base + 0 * CH) = hq;
        *(u64*)(base + 1 * CH) = lq;
    }
    {   // z2 -> B (hi only)
        float4 v = reinterpret_cast<const float4*>(z2 + (size_t)gw * 128)[l];
        float x[4] = {v.x, v.y, v.z, v.w};
        float sq = x[0]*x[0] + x[1]*x[1] + x[2]*x[2] + x[3]*x[3];
        #pragma unroll
        for (int o = 16; o; o >>= 1) sq += __shfl_xor_sync(0xffffffffu, sq, o);
        if (l == 0) g_sq2[gw] = sq;
        u64 hq = 0;
        #pragma unroll
        for (int t = 0; t < 4; t++)
            hq |= (u64)__half_as_ushort(__float2half_rn(x[t])) << (16 * t);
        *(u64*)(g_B + (size_t)rb * BBLK + rowoff) = hq;
    }
}

// ---------------------------------------------------------------------------
// Main: 128 CTAs (64 row-blocks x 2 col-splits), 8 warps, warp tile 64x32.
// acc = hiA.hiB + loA.hiB = dot(x1, hiB): 16 k16 steps sharing one B chunk.
// Fused row-min + diag epilogue, register-resident.
// ---------------------------------------------------------------------------
__global__ __launch_bounds__(256, 1) void tl_gemm_kernel() {
    extern __shared__ char smem[];
    float* partmin = (float*)(smem + SM_PART);
    const float* sq2s = (const float*)(smem + SM_SQ2S);
    const uint32_t smA = smem_u32(smem) + SM_A;
    const uint32_t smB = smem_u32(smem) + SM_B;

    const int tid = threadIdx.x;
    const int l = tid & 31, wid = tid >> 5;
    const int wr = wid & 1, wc = wid >> 1;       // 2 row halves x 4 col groups
    const int rowBase = blockIdx.x * 128;
    const int sp = blockIdx.y;

    // prologue: A block (hi+lo, resident) + sq2 slice + B tile 0
    {
        const unsigned char* Ag = g_A + (size_t)blockIdx.x * ABLK;
        #pragma unroll
        for (int e = 0; e < 17; e++) {               // 4352 x 16B
            int idx = e * 256 + tid;
            cpasync16(smA + idx * 16, Ag + (size_t)idx * 16);
        }
        const float* q2 = g_sq2 + sp * (TILES * 128);
        #pragma unroll
        for (int e = 0; e < 4; e++) {                // 1024 x 16B
            int idx = e * 256 + tid;
            cpasync16(smem_u32(smem) + SM_SQ2S + idx * 16, q2 + idx * 4);
        }
        const unsigned char* Bg = g_B + (size_t)(sp * TILES) * BBLK;
        #pragma unroll
        for (int e = 0; e < 9; e++) {                // 2176 x 16B
            int idx = e * 256 + tid;
            if (idx < CH / 16) cpasync16(smB + idx * 16, Bg + (size_t)idx * 16);
        }
        CP_COMMIT();
    }

    float rminL[4], rminH[4];
    #pragma unroll
    for (int i = 0; i < 4; i++) { rminL[i] = CUDART_INF_F; rminH[i] = CUDART_INF_F; }

    const uint32_t aOff = (uint32_t)((wr * 64 + (l & 15)) * ROWB + (l >> 4) * 16);
    const uint32_t bOff = (uint32_t)((wc * 32 + (l & 15)) * ROWB + (l >> 4) * 16);
    const int mL = rowBase + wr * 64 + (l >> 2);

    float acc[4][4][4];

    for (int jt = 0; jt < TILES; jt++) {
        CP_WAIT0();
        __syncthreads();

        if (jt + 1 < TILES) {   // prefetch next 34KB B chunk
            const unsigned char* Bg = g_B + (size_t)(sp * TILES + jt + 1) * BBLK;
            const uint32_t dst = smB + (uint32_t)(((jt + 1) & 1) ? CH : 0);
            #pragma unroll
            for (int e = 0; e < 9; e++) {
                int idx = e * 256 + tid;
                if (idx < CH / 16) cpasync16(dst + idx * 16, Bg + (size_t)idx * 16);
            }
            CP_COMMIT();
        }

        const uint32_t aHi = smA + aOff, aLo = aHi + CH;
        const uint32_t bC = smB + (uint32_t)((jt & 1) ? CH : 0) + bOff;

        #pragma unroll
        for (int ks = 0; ks < 8; ks++) {
            uint32_t b[8];
            ldsm_x4(bC + ks * 32, b[0], b[1], b[2], b[3]);                 // n0-15
            ldsm_x4(bC + 16 * ROWB + ks * 32, b[4], b[5], b[6], b[7]);     // n16-31
            #pragma unroll
            for (int i = 0; i < 4; i++) {            // hi chain
                uint32_t a0, a1, a2, a3;
                ldsm_x4(aHi + i * 16 * ROWB + ks * 32, a0, a1, a2, a3);
                if (ks == 0) {
                    hmma_z(acc[i][0], a0, a1, a2, a3, b[0], b[2]);
                    hmma_z(acc[i][1], a0, a1, a2, a3, b[1], b[3]);
                    hmma_z(acc[i][2], a0, a1, a2, a3, b[4], b[6]);
                    hmma_z(acc[i][3], a0, a1, a2, a3, b[5], b[7]);
                } else {
                    hmma(acc[i][0], a0, a1, a2, a3, b[0], b[2]);
                    hmma(acc[i][1], a0, a1, a2, a3, b[1], b[3]);
                    hmma(acc[i][2], a0, a1, a2, a3, b[4], b[6]);
                    hmma(acc[i][3], a0, a1, a2, a3, b[5], b[7]);
                }
            }
            #pragma unroll
            for (int i = 0; i < 4; i++) {            // lo chain (same B frags)
                uint32_t a0, a1, a2, a3;
                ldsm_x4(aLo + i * 16 * ROWB + ks * 32, a0, a1, a2, a3);
                hmma(acc[i][0], a0, a1, a2, a3, b[0], b[2]);
                hmma(acc[i][1], a0, a1, a2, a3, b[1], b[3]);
                hmma(acc[i][2], a0, a1, a2, a3, b[4], b[6]);
                hmma(acc[i][3], a0, a1, a2, a3, b[5], b[7]);
            }
        }

        // ---- epilogue: v = sq2 - 2*dot, diag capture, running min
        {
            const int colT = (sp * TILES + jt) * 128;
            const int nb = wc * 32 + 2 * (l & 3);       // local col in tile
            const bool diagT = (colT == rowBase);
            #pragma unroll
            for (int j = 0; j < 4; j++) {
                const int nl = nb + j * 8;
                const int n0 = colT + nl;
                const float2 q2 = *(const float2*)(sq2s + jt * 128 + nl);
                #pragma unroll
                for (int i = 0; i < 4; i++) {
                    float v0 = q2.x - 2.f * acc[i][j][0];
                    float v1 = q2.y - 2.f * acc[i][j][1];
                    float v2 = q2.x - 2.f * acc[i][j][2];
                    float v3 = q2.y - 2.f * acc[i][j][3];
                    if (diagT) {
                        const int m0 = mL + i * 16, m1 = m0 + 8;
                        if (n0 == m0)     { g_posv[m0] = v0; v0 = CUDART_INF_F; }
                        if (n0 + 1 == m0) { g_posv[m0] = v1; v1 = CUDART_INF_F; }
                        if (n0 == m1)     { g_posv[m1] = v2; v2 = CUDART_INF_F; }
                        if (n0 + 1 == m1) { g_posv[m1] = v3; v3 = CUDART_INF_F; }
                    }
                    rminL[i] = fminf(rminL[i], fminf(v0, v1));
                    rminH[i] = fminf(rminH[i], fminf(v2, v3));
                }
            }
        }
    }

    // cross-lane then cross-warp-column min reduction
    #pragma unroll
    for (int i = 0; i < 4; i++) {
        float vL = rminL[i], vH = rminH[i];
        vL = fminf(vL, __shfl_xor_sync(0xffffffffu, vL, 1));
        vL = fminf(vL, __shfl_xor_sync(0xffffffffu, vL, 2));
        vH = fminf(vH, __shfl_xor_sync(0xffffffffu, vH, 1));
        vH = fminf(vH, __shfl_xor_sync(0xffffffffu, vH, 2));
        if ((l & 3) == 0) {
            const int r = wr * 64 + i * 16 + (l >> 2);
            partmin[wc * 128 + r]     = vL;
            partmin[wc * 128 + r + 8] = vH;
        }
    }
    __syncthreads();
    if (tid < 128) {
        float m = fminf(fminf(partmin[tid], partmin[128 + tid]),
                        fminf(partmin[256 + tid], partmin[384 + tid]));
        g_rowmin[sp][rowBase + tid] = m;
    }
}

// ---------------------------------------------------------------------------
__global__ void finalize_kernel(float* __restrict__ out) {
    __shared__ float red[256];
    const int tid = threadIdx.x;
    float s = 0.f;
    for (int i = tid; i < NROWS; i += 256) {
        float m = fminf(g_rowmin[0][i], g_rowmin[1][i]);
        const float sq1 = g_sq1[i];
        const float l = sqrtf(fmaxf(sq1 + g_posv[i], 0.f))
                      - sqrtf(fmaxf(sq1 + m, 0.f)) + MARGIN_F;
        s += fmaxf(l, 0.f);
    }
    red[tid] = s;
    __syncthreads();
    #pragma unroll
    for (int o = 128; o; o >>= 1) {
        if (tid < o) red[tid] += red[tid + o];
        __syncthreads();
    }
    if (tid == 0) out[0] = red[0] / (float)NROWS;
}

// ---------------------------------------------------------------------------
extern "C" void kernel_launch(void* const* d_in, const int* in_sizes, int n_in,
                              void* d_out, int out_size) {
    const float* z1 = (const float*)d_in[0];
    const float* z2 = (const float*)d_in[1];
    float* out = (float*)d_out;

    cudaFuncSetAttribute(tl_gemm_kernel,
                         cudaFuncAttributeMaxDynamicSharedMemorySize, SMEM_TOTAL);

    prep_kernel<<<NROWS / 8, 256>>>(z1, z2);
    tl_gemm_kernel<<<dim3(64, NSPLIT), 256, SMEM_TOTAL>>>();
    finalize_kernel<<<1, 256>>>(out);
}

// round 6
// speedup vs baseline: 4.9271x; 1.4411x over previous
#include <cuda_runtime.h>
#include <cuda_fp16.h>
#include <math_constants.h>
#include <cstdint>

#define NROWS 8192
#define NSPLIT 2
#define TILES 32                  // 128-wide col tiles per split
#define MARGIN_F 0.3f

#define ROWB 272                  // padded row stride bytes (256 used) -> conflict-free ldsm
#define CH (128 * ROWB)           // 34816 B per 128x128 fp16 chunk

// smem map
#define SM_PART 0                           // 4*128 floats = 2048
#define SM_SQ2S 2048                        // 4096 floats = 16384
#define SM_A    (SM_SQ2S + 16384)           // 34816 (resident)
#define SM_B    (SM_A + CH)                 // 2 x 34816 (double buffer)
#define SMEM_TOTAL (SM_B + 2 * CH)          // 122880

typedef unsigned long long u64;

__device__ __align__(16) unsigned char g_A[64 * CH];   // 2.1 MB (hi fp16)
__device__ __align__(16) unsigned char g_B[64 * CH];   // 2.1 MB
__device__ float g_sq1[NROWS];
__device__ float g_sq2[NROWS];
__device__ float g_posd2[NROWS];            // exact |z1_i - z2_i|^2
__device__ float g_rowmin[NSPLIT][NROWS];

__device__ __forceinline__ uint32_t smem_u32(const void* p) {
    uint32_t a;
    asm("{ .reg .u64 t; cvta.to.shared.u64 t, %1; cvt.u32.u64 %0, t; }" : "=r"(a) : "l"(p));
    return a;
}
__device__ __forceinline__ void cpasync16(uint32_t dst, const void* src) {
    asm volatile("cp.async.cg.shared.global [%0], [%1], 16;" :: "r"(dst), "l"(src));
}
#define CP_COMMIT() asm volatile("cp.async.commit_group;" ::: "memory")
#define CP_WAIT0()  asm volatile("cp.async.wait_group 0;"  ::: "memory")

__device__ __forceinline__ void ldsm_x4(uint32_t addr, uint32_t& r0, uint32_t& r1,
                                        uint32_t& r2, uint32_t& r3) {
    asm volatile("ldmatrix.sync.aligned.m8n8.x4.shared.b16 {%0,%1,%2,%3}, [%4];"
                 : "=r"(r0), "=r"(r1), "=r"(r2), "=r"(r3) : "r"(addr));
}
__device__ __forceinline__ void hmma(float* c, uint32_t a0, uint32_t a1, uint32_t a2,
                                     uint32_t a3, uint32_t b0, uint32_t b1) {
    asm volatile("mma.sync.aligned.m16n8k16.row.col.f32.f16.f16.f32 "
                 "{%0,%1,%2,%3}, {%4,%5,%6,%7}, {%8,%9}, {%0,%1,%2,%3};"
                 : "+f"(c[0]), "+f"(c[1]), "+f"(c[2]), "+f"(c[3])
                 : "r"(a0), "r"(a1), "r"(a2), "r"(a3), "r"(b0), "r"(b1));
}
__device__ __forceinline__ void hmma_z(float* c, uint32_t a0, uint32_t a1, uint32_t a2,
                                       uint32_t a3, uint32_t b0, uint32_t b1) {
    asm volatile("mma.sync.aligned.m16n8k16.row.col.f32.f16.f16.f32 "
                 "{%0,%1,%2,%3}, {%4,%5,%6,%7}, {%8,%9}, {%10,%10,%10,%10};"
                 : "=f"(c[0]), "=f"(c[1]), "=f"(c[2]), "=f"(c[3])
                 : "r"(a0), "r"(a1), "r"(a2), "r"(a3), "r"(b0), "r"(b1), "f"(0.f));
}

// ---------------------------------------------------------------------------
// Prep: one warp per row. sq norms, EXACT pos d2 = |z1-z2|^2, fp16 hi images.
// ---------------------------------------------------------------------------
__global__ void prep_kernel(const float* __restrict__ z1, const float* __restrict__ z2) {
    const int gw = (blockIdx.x * blockDim.x + threadIdx.x) >> 5;
    const int l  = threadIdx.x & 31;
    if (gw >= NROWS) return;
    const int rb = gw >> 7, r = gw & 127;
    const size_t rowoff = (size_t)rb * CH + (size_t)r * ROWB + (size_t)l * 8;

    float4 v1 = reinterpret_cast<const float4*>(z1 + (size_t)gw * 128)[l];
    float4 v2 = reinterpret_cast<const float4*>(z2 + (size_t)gw * 128)[l];
    float x1[4] = {v1.x, v1.y, v1.z, v1.w};
    float x2[4] = {v2.x, v2.y, v2.z, v2.w};

    float sq1 = 0.f, sq2 = 0.f, dd = 0.f;
    u64 hq1 = 0, hq2 = 0;
    #pragma unroll
    for (int t = 0; t < 4; t++) {
        sq1 += x1[t] * x1[t];
        sq2 += x2[t] * x2[t];
        const float d = x1[t] - x2[t];
        dd += d * d;
        hq1 |= (u64)__half_as_ushort(__float2half_rn(x1[t])) << (16 * t);
        hq2 |= (u64)__half_as_ushort(__float2half_rn(x2[t])) << (16 * t);
    }
    #pragma unroll
    for (int o = 16; o; o >>= 1) {
        sq1 += __shfl_xor_sync(0xffffffffu, sq1, o);
        sq2 += __shfl_xor_sync(0xffffffffu, sq2, o);
        dd  += __shfl_xor_sync(0xffffffffu, dd, o);
    }
    *(u64*)(g_A + rowoff) = hq1;
    *(u64*)(g_B + rowoff) = hq2;
    if (l == 0) { g_sq1[gw] = sq1; g_sq2[gw] = sq2; g_posd2[gw] = dd; }
}

// ---------------------------------------------------------------------------
// Main: 128 CTAs (64 row-blocks x 2 col-splits), 8 warps, warp tile 64x32.
// Single fp16 chain K=128: 8 k16 steps/tile. Fused row-min epilogue.
// ---------------------------------------------------------------------------
__global__ __launch_bounds__(256, 1) void tl_gemm_kernel() {
    extern __shared__ char smem[];
    float* partmin = (float*)(smem + SM_PART);
    const float* sq2s = (const float*)(smem + SM_SQ2S);
    const uint32_t smA = smem_u32(smem) + SM_A;
    const uint32_t smB = smem_u32(smem) + SM_B;

    const int tid = threadIdx.x;
    const int l = tid & 31, wid = tid >> 5;
    const int wr = wid & 1, wc = wid >> 1;       // 2 row halves x 4 col groups
    const int rowBase = blockIdx.x * 128;
    const int sp = blockIdx.y;

    // prologue: A chunk (resident) + sq2 slice + B tile 0
    {
        const unsigned char* Ag = g_A + (size_t)blockIdx.x * CH;
        #pragma unroll
        for (int e = 0; e < 9; e++) {                // 2176 x 16B
            int idx = e * 256 + tid;
            if (idx < CH / 16) cpasync16(smA + idx * 16, Ag + (size_t)idx * 16);
        }
        const float* q2 = g_sq2 + sp * (TILES * 128);
        #pragma unroll
        for (int e = 0; e < 4; e++) {                // 1024 x 16B
            int idx = e * 256 + tid;
            cpasync16(smem_u32(smem) + SM_SQ2S + idx * 16, q2 + idx * 4);
        }
        const unsigned char* Bg = g_B + (size_t)(sp * TILES) * CH;
        #pragma unroll
        for (int e = 0; e < 9; e++) {
            int idx = e * 256 + tid;
            if (idx < CH / 16) cpasync16(smB + idx * 16, Bg + (size_t)idx * 16);
        }
        CP_COMMIT();
    }

    float rminL[4], rminH[4];
    #pragma unroll
    for (int i = 0; i < 4; i++) { rminL[i] = CUDART_INF_F; rminH[i] = CUDART_INF_F; }

    const uint32_t aOff = (uint32_t)((wr * 64 + (l & 15)) * ROWB + (l >> 4) * 16);
    const uint32_t bOff = (uint32_t)((wc * 32 + (l & 15)) * ROWB + (l >> 4) * 16);
    const int mL = rowBase + wr * 64 + (l >> 2);

    float acc[4][4][4];

    for (int jt = 0; jt < TILES; jt++) {
        CP_WAIT0();
        __syncthreads();

        if (jt + 1 < TILES) {   // prefetch next 34KB B chunk
            const unsigned char* Bg = g_B + (size_t)(sp * TILES + jt + 1) * CH;
            const uint32_t dst = smB + (uint32_t)(((jt + 1) & 1) ? CH : 0);
            #pragma unroll
            for (int e = 0; e < 9; e++) {
                int idx = e * 256 + tid;
                if (idx < CH / 16) cpasync16(dst + idx * 16, Bg + (size_t)idx * 16);
            }
            CP_COMMIT();
        }

        const uint32_t aHi = smA + aOff;
        const uint32_t bC = smB + (uint32_t)((jt & 1) ? CH : 0) + bOff;

        #pragma unroll
        for (int ks = 0; ks < 8; ks++) {
            uint32_t b[8];
            ldsm_x4(bC + ks * 32, b[0], b[1], b[2], b[3]);                 // n0-15
            ldsm_x4(bC + 16 * ROWB + ks * 32, b[4], b[5], b[6], b[7]);     // n16-31
            #pragma unroll
            for (int i = 0; i < 4; i++) {
                uint32_t a0, a1, a2, a3;
                ldsm_x4(aHi + i * 16 * ROWB + ks * 32, a0, a1, a2, a3);
                if (ks == 0) {
                    hmma_z(acc[i][0], a0, a1, a2, a3, b[0], b[2]);
                    hmma_z(acc[i][1], a0, a1, a2, a3, b[1], b[3]);
                    hmma_z(acc[i][2], a0, a1, a2, a3, b[4], b[6]);
                    hmma_z(acc[i][3], a0, a1, a2, a3, b[5], b[7]);
                } else {
                    hmma(acc[i][0], a0, a1, a2, a3, b[0], b[2]);
                    hmma(acc[i][1], a0, a1, a2, a3, b[1], b[3]);
                    hmma(acc[i][2], a0, a1, a2, a3, b[4], b[6]);
                    hmma(acc[i][3], a0, a1, a2, a3, b[5], b[7]);
                }
            }
        }

        // ---- epilogue: v = sq2 - 2*dot, inf-mask diagonal, running min
        {
            const int colT = (sp * TILES + jt) * 128;
            const int nb = wc * 32 + 2 * (l & 3);       // local col in tile
            const bool diagT = (colT == rowBase);
            #pragma unroll
            for (int j = 0; j < 4; j++) {
                const int nl = nb + j * 8;
                const int n0 = colT + nl;
                const float2 q2 = *(const float2*)(sq2s + jt * 128 + nl);
                #pragma unroll
                for (int i = 0; i < 4; i++) {
                    float v0 = q2.x - 2.f * acc[i][j][0];
                    float v1 = q2.y - 2.f * acc[i][j][1];
                    float v2 = q2.x - 2.f * acc[i][j][2];
                    float v3 = q2.y - 2.f * acc[i][j][3];
                    if (diagT) {
                        const int m0 = mL + i * 16, m1 = m0 + 8;
                        if (n0 == m0)     v0 = CUDART_INF_F;
                        if (n0 + 1 == m0) v1 = CUDART_INF_F;
                        if (n0 == m1)     v2 = CUDART_INF_F;
                        if (n0 + 1 == m1) v3 = CUDART_INF_F;
                    }
                    rminL[i] = fminf(rminL[i], fminf(v0, v1));
                    rminH[i] = fminf(rminH[i], fminf(v2, v3));
                }
            }
        }
    }

    // cross-lane then cross-warp-column min reduction
    #pragma unroll
    for (int i = 0; i < 4; i++) {
        float vL = rminL[i], vH = rminH[i];
        vL = fminf(vL, __shfl_xor_sync(0xffffffffu, vL, 1));
        vL = fminf(vL, __shfl_xor_sync(0xffffffffu, vL, 2));
        vH = fminf(vH, __shfl_xor_sync(0xffffffffu, vH, 1));
        vH = fminf(vH, __shfl_xor_sync(0xffffffffu, vH, 2));
        if ((l & 3) == 0) {
            const int r = wr * 64 + i * 16 + (l >> 2);
            partmin[wc * 128 + r]     = vL;
            partmin[wc * 128 + r + 8] = vH;
        }
    }
    __syncthreads();
    if (tid < 128) {
        float m = fminf(fminf(partmin[tid], partmin[128 + tid]),
                        fminf(partmin[256 + tid], partmin[384 + tid]));
        g_rowmin[sp][rowBase + tid] = m;
    }
}

// ---------------------------------------------------------------------------
__global__ void finalize_kernel(float* __restrict__ out) {
    __shared__ float red[256];
    const int tid = threadIdx.x;
    float s = 0.f;
    for (int i = tid; i < NROWS; i += 256) {
        float m = fminf(g_rowmin[0][i], g_rowmin[1][i]);
        const float l = sqrtf(fmaxf(g_posd2[i], 0.f))
                      - sqrtf(fmaxf(g_sq1[i] + m, 0.f)) + MARGIN_F;
        s += fmaxf(l, 0.f);
    }
    red[tid] = s;
    __syncthreads();
    #pragma unroll
    for (int o = 128; o; o >>= 1) {
        if (tid < o) red[tid] += red[tid + o];
        __syncthreads();
    }
    if (tid == 0) out[0] = red[0] / (float)NROWS;
}

// ---------------------------------------------------------------------------
extern "C" void kernel_launch(void* const* d_in, const int* in_sizes, int n_in,
                              void* d_out, int out_size) {
    const float* z1 = (const float*)d_in[0];
    const float* z2 = (const float*)d_in[1];
    float* out = (float*)d_out;

    cudaFuncSetAttribute(tl_gemm_kernel,
                         cudaFuncAttributeMaxDynamicSharedMemorySize, SMEM_TOTAL);

    prep_kernel<<<NROWS / 8, 256>>>(z1, z2);
    tl_gemm_kernel<<<dim3(64, NSPLIT), 256, SMEM_TOTAL>>>();
    finalize_kernel<<<1, 256>>>(out);
}